// round 6
// baseline (speedup 1.0000x reference)
#include <cuda_runtime.h>
#include <cuda_fp16.h>
#include <math.h>

#define NB 16
#define NV 256
#define NR 1024
#define RMASK 1023

// OS-CFAR intermediate: half2 packs two adjacent v-rows; values pre-scaled by alpha/16. 8.4 MB.
__device__ __half2 g_os2[(NB * NV / 2) * NR];

#define CAS2(a, b) do { __half2 _hi = __hmax2(a, b); __half2 _lo = __hmin2(a, b); (a) = _hi; (b) = _lo; } while (0)

__device__ __forceinline__ __half2 shfl_dn_h2(__half2 v, int delta) {
    unsigned u = __shfl_down_sync(0xffffffffu, *(unsigned*)&v, delta);
    return *(__half2*)&u;
}

// Batcher odd-even mergesort, 8 elems, descending (19 comparators).
__device__ __forceinline__ void sort8h(__half2* x) {
    CAS2(x[0], x[1]); CAS2(x[2], x[3]); CAS2(x[0], x[2]); CAS2(x[1], x[3]); CAS2(x[1], x[2]);
    CAS2(x[4], x[5]); CAS2(x[6], x[7]); CAS2(x[4], x[6]); CAS2(x[5], x[7]); CAS2(x[5], x[6]);
    CAS2(x[0], x[4]); CAS2(x[2], x[6]); CAS2(x[2], x[4]);
    CAS2(x[1], x[5]); CAS2(x[3], x[7]); CAS2(x[3], x[5]);
    CAS2(x[1], x[2]); CAS2(x[3], x[4]); CAS2(x[5], x[6]);
}

// M = sorted-desc top-8 of (sorted a) U (sorted b): half-cleaner + bitonic sort-8.
__device__ __forceinline__ void merge_top8(const __half2* a, const __half2* b, __half2* m) {
    m[0] = __hmax2(a[0], b[7]); m[1] = __hmax2(a[1], b[6]);
    m[2] = __hmax2(a[2], b[5]); m[3] = __hmax2(a[3], b[4]);
    m[4] = __hmax2(a[4], b[3]); m[5] = __hmax2(a[5], b[2]);
    m[6] = __hmax2(a[6], b[1]); m[7] = __hmax2(a[7], b[0]);
    CAS2(m[0], m[4]); CAS2(m[1], m[5]); CAS2(m[2], m[6]); CAS2(m[3], m[7]);
    CAS2(m[0], m[2]); CAS2(m[1], m[3]); CAS2(m[4], m[6]); CAS2(m[5], m[7]);
    CAS2(m[0], m[1]); CAS2(m[2], m[3]); CAS2(m[4], m[5]); CAS2(m[6], m[7]);
}

// 8th largest of union of two sorted-desc-8 lists = min_i max(A[i], B[7-i]).
__device__ __forceinline__ __half2 kth8(const __half2* a, const __half2* b) {
    __half2 m0 = __hmin2(__hmax2(a[0], b[7]), __hmax2(a[1], b[6]));
    __half2 m1 = __hmin2(__hmax2(a[2], b[5]), __hmax2(a[3], b[4]));
    __half2 m2 = __hmin2(__hmax2(a[4], b[3]), __hmax2(a[5], b[2]));
    __half2 m3 = __hmin2(__hmax2(a[6], b[1]), __hmax2(a[7], b[0]));
    return __hmin2(__hmin2(m0, m1), __hmin2(m2, m3));
}

// Spill row stride: 18 half2 (72B) -> 18 words, gcd(18,32)=2 but only <=13 active lanes
// at stride 18 words never alias a bank: conflict-free.
#define SP 18

// OS kernel v4: shuffle-exchange. One block per v-row pair; 512 threads (16 warps);
// thread t owns positions p = 2t, 2t+1.
//   L(2t+8),L(2t+9)  = La,Lb of thread t+4   -> shfl_down 4  (lanes 28-31 via smem spill)
//   M(2t+25)         = M1 of thread t+12     -> shfl_down 12 (lanes >=20 via spill)
//   M(2t+26)         = M0 of thread t+13     -> shfl_down 13 (lanes >=19 via spill)
// Input pre-scaled by alpha/16 (min/max commute with positive scale; /16 is the CA divisor).
__global__ void __launch_bounds__(512, 2) os4_kernel(const float* __restrict__ data, float ae) {
    __shared__ __half2 row2[1040];
    __shared__ __half2 Lsp[16 * 4 * SP];    // [warp][lane0..3]: La[8] | Lb[8]
    __shared__ __half2 Msp[16 * 13 * 2 * SP / 2]; // [warp][lane0..12]: M0[8] | M1[8] (16 half2 per row, SP-strided pairs)

    const int t = threadIdx.x;
    const int w = t >> 5, l = t & 31;
    const float2* srcA = (const float2*)(data + (size_t)(2 * blockIdx.x) * NR);
    const float2* srcB = (const float2*)(data + (size_t)(2 * blockIdx.x + 1) * NR);

    {   // load + scale + pack
        float2 fa = srcA[t], fb = srcB[t];
        __half2 h0 = __floats2half2_rn(fa.x * ae, fb.x * ae);
        __half2 h1 = __floats2half2_rn(fa.y * ae, fb.y * ae);
        row2[2 * t]     = h0;
        row2[2 * t + 1] = h1;
        if (t < 8) { row2[1024 + 2 * t] = h0; row2[1024 + 2 * t + 1] = h1; }
    }
    __syncthreads();

    // Phase A: sort L(2t), L(2t+1) in registers.
    __half2 r[10];
    {
        const uint2* rp = (const uint2*)(row2 + 2 * t);
#pragma unroll
        for (int k = 0; k < 5; k++) {
            uint2 q = rp[k];
            r[2 * k]     = *(__half2*)&q.x;
            r[2 * k + 1] = *(__half2*)&q.y;
        }
    }
    __half2 La[8], Lb[8];
#pragma unroll
    for (int i = 0; i < 8; i++) { La[i] = r[i]; Lb[i] = r[i + 1]; }
    sort8h(La);
    sort8h(Lb);

    // Spill L of lanes 0-3 (needed by previous warp's lanes 28-31).
    if (l < 4) {
        __half2* s = &Lsp[(w * 4 + l) * SP];
#pragma unroll
        for (int i = 0; i < 8; i++) { s[i] = La[i]; s[i + 8] = Lb[i]; }
    }
    __syncthreads();

    // Phase B: fetch L(2t+8), L(2t+9) via shuffle (or spill at warp boundary), merge.
    __half2 xb[8], yb[8];
#pragma unroll
    for (int i = 0; i < 8; i++) {
        xb[i] = shfl_dn_h2(La[i], 4);
        yb[i] = shfl_dn_h2(Lb[i], 4);
    }
    if (l >= 28) {
        const __half2* s = &Lsp[(((w + 1) & 15) * 4 + (l - 28)) * SP];
#pragma unroll
        for (int i = 0; i < 8; i++) { xb[i] = s[i]; yb[i] = s[i + 8]; }
    }
    __half2 M0[8], M1[8];
    merge_top8(La, xb, M0);
    merge_top8(Lb, yb, M1);

    // Spill M of lanes 0-12 (needed by previous warp's lanes >=19).
    if (l < 13) {
        __half2* s = &Msp[(w * 13 + l) * SP];
#pragma unroll
        for (int i = 0; i < 8; i++) { s[i] = M0[i]; s[i + 8] = M1[i]; }
    }
    __syncthreads();

    // Phase C: n0 = M(2t+25) = M1 of t+12; n1 = M(2t+26) = M0 of t+13.
    __half2 n0[8], n1[8];
#pragma unroll
    for (int i = 0; i < 8; i++) {
        n0[i] = shfl_dn_h2(M1[i], 12);
        n1[i] = shfl_dn_h2(M0[i], 13);
    }
    if (l >= 20) {
        const __half2* s = &Msp[(((w + 1) & 15) * 13 + (l - 20)) * SP];
#pragma unroll
        for (int i = 0; i < 8; i++) n0[i] = s[i + 8];
    }
    if (l >= 19) {
        const __half2* s = &Msp[(((w + 1) & 15) * 13 + (l - 19)) * SP];
#pragma unroll
        for (int i = 0; i < 8; i++) n1[i] = s[i];
    }

    __half2 os0 = kth8(M0, n0);
    __half2 os1 = kth8(M1, n1);

    __half2* g2 = g_os2 + (size_t)blockIdx.x * NR;
    const int rr = (2 * t + 20) & RMASK;   // even; rr+1 adjacent
    uint2 o; o.x = *(unsigned*)&os0; o.y = *(unsigned*)&os1;
    *(uint2*)&g2[rr] = o;
}

// CA kernel (round-3 best-measured form, half2 source): out(v) = box21(v) - box5(v),
// alpha/16 pre-folded. Block = (batch, 32-wide r chunk); tile unpacked fp32 in smem.
__global__ void __launch_bounds__(512) ca_kernel(float* __restrict__ out) {
    __shared__ float tile[NV][32];
    const int b  = blockIdx.x >> 5;
    const int r0 = (blockIdx.x & 31) * 32;
    const int t  = threadIdx.x;

    const __half2* src = g_os2 + (size_t)b * (NV / 2) * NR + r0;
#pragma unroll
    for (int i = 0; i < 8; i++) {
        int idx = t + 512 * i;             // 0..4095 -> 128 vp x 32 rl
        int vp = idx >> 5, rl = idx & 31;
        __half2 v2 = src[(size_t)vp * NR + rl];
        tile[2 * vp][rl]     = __low2float(v2);
        tile[2 * vp + 1][rl] = __high2float(v2);
    }
    __syncthreads();

    const int rl = t & 31;
    const int v0 = (t >> 5) * 16;

    float box21 = 0.0f, box5 = 0.0f;
#pragma unroll
    for (int d = -10; d <= 10; d++) {
        float x = tile[(v0 + d) & (NV - 1)][rl];
        box21 += x;
        if (d >= -2 && d <= 2) box5 += x;
    }

    float* dst = out + (size_t)b * NV * NR + r0 + rl;
#pragma unroll
    for (int vi = 0; vi < 16; vi++) {
        const int v = v0 + vi;
        dst[(size_t)v * NR] = box21 - box5;
        box21 += tile[(v + 11) & (NV - 1)][rl] - tile[(v - 10) & (NV - 1)][rl];
        box5  += tile[(v + 3)  & (NV - 1)][rl] - tile[(v - 2)  & (NV - 1)][rl];
    }
}

// ---------------- host: replicate the reference's alpha solve ----------------

static double cfar_log_factorial(double n) {
    n += 1.0;
    if (n < 9.0) {
        double f = 1.0;
        int m = (int)(n + 0.5);
        for (int i = 2; i <= m; i++) f *= (double)i;
        return log(f);
    }
    return 0.5 * (log(2.0 * 3.14159265358979323846) - log(n))
         + n * (log(n + 1.0 / (12.0 * n - 1.0 / (10.0 * n))) - 1.0);
}

static double cfar_fun(int k, int n, double t, double pfa) {
    double s = 0.0;
    for (int j = n; j > n - k; j--) s += log((double)j + t);
    return cfar_log_factorial((double)n) - cfar_log_factorial((double)(n - k)) - s - log(pfa);
}

extern "C" void kernel_launch(void* const* d_in, const int* in_sizes, int n_in,
                              void* d_out, int out_size) {
    (void)in_sizes; (void)n_in; (void)out_size;
    const float* data = (const float*)d_in[0];
    float* out = (float*)d_out;

    double lo = 1.0, hi = 1.0e6;
    for (int it = 0; it < 200; it++) {
        double mid = 0.5 * (lo + hi);
        if (cfar_fun(24, 32, mid, 1.0e-5) > 0.0) lo = mid; else hi = mid;
    }
    float alpha_eff = (float)(sqrt(0.5 * (lo + hi)) / 16.0);   // alpha/16, CA divisor folded

    os4_kernel<<<NB * NV / 2, 512>>>(data, alpha_eff);
    ca_kernel<<<NB * 32, 512>>>(out);
}

// round 7
// speedup vs baseline: 1.1645x; 1.1645x over previous
#include <cuda_runtime.h>
#include <cuda_fp16.h>
#include <math.h>

#define NB 16
#define NV 256
#define NR 1024
#define RMASK 1023
#define CS 1056          // table position stride (1024 + wrap extension), even

// OS-CFAR intermediate: half2 packs two adjacent v-rows; values pre-scaled by alpha/16. 8.4 MB.
__device__ __half2 g_os2[(NB * NV / 2) * NR];

#define CAS2(a, b) do { __half2 _hi = __hmax2(a, b); __half2 _lo = __hmin2(a, b); (a) = _hi; (b) = _lo; } while (0)

__device__ __forceinline__ __half2 u2h(unsigned u) { return *(__half2*)&u; }
__device__ __forceinline__ unsigned h2u(__half2 h) { return *(unsigned*)&h; }

// Batcher odd-even mergesort, 8 elems, descending (19 comparators).
__device__ __forceinline__ void sort8h(__half2* x) {
    CAS2(x[0], x[1]); CAS2(x[2], x[3]); CAS2(x[0], x[2]); CAS2(x[1], x[3]); CAS2(x[1], x[2]);
    CAS2(x[4], x[5]); CAS2(x[6], x[7]); CAS2(x[4], x[6]); CAS2(x[5], x[7]); CAS2(x[5], x[6]);
    CAS2(x[0], x[4]); CAS2(x[2], x[6]); CAS2(x[2], x[4]);
    CAS2(x[1], x[5]); CAS2(x[3], x[7]); CAS2(x[3], x[5]);
    CAS2(x[1], x[2]); CAS2(x[3], x[4]); CAS2(x[5], x[6]);
}

// M = sorted-desc top-8 of (sorted a) U (sorted b): half-cleaner + bitonic sort-8.
__device__ __forceinline__ void merge_top8(const __half2* a, const __half2* b, __half2* m) {
    m[0] = __hmax2(a[0], b[7]); m[1] = __hmax2(a[1], b[6]);
    m[2] = __hmax2(a[2], b[5]); m[3] = __hmax2(a[3], b[4]);
    m[4] = __hmax2(a[4], b[3]); m[5] = __hmax2(a[5], b[2]);
    m[6] = __hmax2(a[6], b[1]); m[7] = __hmax2(a[7], b[0]);
    CAS2(m[0], m[4]); CAS2(m[1], m[5]); CAS2(m[2], m[6]); CAS2(m[3], m[7]);
    CAS2(m[0], m[2]); CAS2(m[1], m[3]); CAS2(m[4], m[6]); CAS2(m[5], m[7]);
    CAS2(m[0], m[1]); CAS2(m[2], m[3]); CAS2(m[4], m[5]); CAS2(m[6], m[7]);
}

// 8th largest of union of two sorted-desc-8 lists = min_i max(A[i], B[7-i]).
__device__ __forceinline__ __half2 kth8(const __half2* a, const __half2* b) {
    __half2 m0 = __hmin2(__hmax2(a[0], b[7]), __hmax2(a[1], b[6]));
    __half2 m1 = __hmin2(__hmax2(a[2], b[5]), __hmax2(a[3], b[4]));
    __half2 m2 = __hmin2(__hmax2(a[4], b[3]), __hmax2(a[5], b[2]));
    __half2 m3 = __hmin2(__hmax2(a[6], b[1]), __hmax2(a[7], b[0]));
    return __hmin2(__hmin2(m0, m1), __hmin2(m2, m3));
}

// OS kernel v5: os3 structure with uint4-packed exchange tables.
// Table layout (half2 units): T[(c2*CS + p)*2 + j] = list(p)[2*c2 + j], so a uint4 at
// even p holds {list(p)[2c2], list(p)[2c2+1], list(p+1)[2c2], list(p+1)[2c2+1]}.
// Thread t owns positions p = 2t, 2t+1; emits r = 2t+20, 2t+21.
__global__ void __launch_bounds__(512, 2) os5_kernel(const float* __restrict__ data, float ae) {
    extern __shared__ unsigned char sm[];
    __half2* row2 = (__half2*)sm;                         // 1040 half2 = 4160 B
    __half2* Lt   = (__half2*)(sm + 4160);                // 4*CS*2 half2 = 33792 B
    __half2* Mt   = (__half2*)(sm + 4160 + 33792);        // 33792 B

    const int t = threadIdx.x;
    const float2* srcA = (const float2*)(data + (size_t)(2 * blockIdx.x) * NR);
    const float2* srcB = (const float2*)(data + (size_t)(2 * blockIdx.x + 1) * NR);

    {   // load + scale + pack
        float2 fa = srcA[t], fb = srcB[t];
        __half2 h0 = __floats2half2_rn(fa.x * ae, fb.x * ae);
        __half2 h1 = __floats2half2_rn(fa.y * ae, fb.y * ae);
        row2[2 * t]     = h0;
        row2[2 * t + 1] = h1;
        if (t < 8) { row2[1024 + 2 * t] = h0; row2[1024 + 2 * t + 1] = h1; }
    }
    __syncthreads();

    // Phase A: sort L(2t), L(2t+1) in registers; publish packed.
    __half2 r[10];
    {
        const uint2* rp = (const uint2*)(row2 + 2 * t);
#pragma unroll
        for (int k = 0; k < 5; k++) {
            uint2 q = rp[k];
            r[2 * k]     = u2h(q.x);
            r[2 * k + 1] = u2h(q.y);
        }
    }
    __half2 La[8], Lb[8];
#pragma unroll
    for (int i = 0; i < 8; i++) { La[i] = r[i]; Lb[i] = r[i + 1]; }
    sort8h(La);
    sort8h(Lb);
#pragma unroll
    for (int c2 = 0; c2 < 4; c2++) {
        uint4 w;
        w.x = h2u(La[2 * c2]); w.y = h2u(La[2 * c2 + 1]);
        w.z = h2u(Lb[2 * c2]); w.w = h2u(Lb[2 * c2 + 1]);
        *(uint4*)(Lt + (c2 * CS + 2 * t) * 2) = w;
        if (t < 4) *(uint4*)(Lt + (c2 * CS + 2 * t + 1024) * 2) = w;   // wrap dup p<8
    }
    __syncthreads();

    // Phase B: M(p) = merge(L(p) [regs], L(p+8) [one LDS.128 per c-pair]).
    __half2 xb[8], yb[8];
#pragma unroll
    for (int c2 = 0; c2 < 4; c2++) {
        uint4 q = *(const uint4*)(Lt + (c2 * CS + 2 * t + 8) * 2);
        xb[2 * c2] = u2h(q.x); xb[2 * c2 + 1] = u2h(q.y);
        yb[2 * c2] = u2h(q.z); yb[2 * c2 + 1] = u2h(q.w);
    }
    __half2 M0[8], M1[8];
    merge_top8(La, xb, M0);
    merge_top8(Lb, yb, M1);
#pragma unroll
    for (int c2 = 0; c2 < 4; c2++) {
        uint4 w;
        w.x = h2u(M0[2 * c2]); w.y = h2u(M0[2 * c2 + 1]);
        w.z = h2u(M1[2 * c2]); w.w = h2u(M1[2 * c2 + 1]);
        *(uint4*)(Mt + (c2 * CS + 2 * t) * 2) = w;
        if (t < 13) *(uint4*)(Mt + (c2 * CS + 2 * t + 1024) * 2) = w;  // wrap dup p<26
    }
    __syncthreads();

    // Phase C: n0 = M(2t+25), n1 = M(2t+26) via LDS.64 pairs.
    __half2 n0[8], n1[8];
#pragma unroll
    for (int c2 = 0; c2 < 4; c2++) {
        uint2 qa = *(const uint2*)(Mt + (c2 * CS + 2 * t + 25) * 2);
        n0[2 * c2] = u2h(qa.x); n0[2 * c2 + 1] = u2h(qa.y);
        uint2 qb = *(const uint2*)(Mt + (c2 * CS + 2 * t + 26) * 2);
        n1[2 * c2] = u2h(qb.x); n1[2 * c2 + 1] = u2h(qb.y);
    }

    __half2 os0 = kth8(M0, n0);
    __half2 os1 = kth8(M1, n1);

    __half2* g2 = g_os2 + (size_t)blockIdx.x * NR;
    const int rr = (2 * t + 20) & RMASK;   // even; rr+1 adjacent
    uint2 o; o.x = h2u(os0); o.y = h2u(os1);
    *(uint2*)&g2[rr] = o;
}

// CA kernel v3: float2 r-pair recurrence. Block = (batch, 32-wide r chunk), 512 threads.
// tile[v][rlp] holds (x@r, x@r+1); thread slides an 8-long v run for one r-pair.
// out(v) = box21(v) - box5(v); alpha/16 pre-folded upstream.
__global__ void __launch_bounds__(512) ca3_kernel(float* __restrict__ out) {
    __shared__ float2 tile[NV][16];
    const int b  = blockIdx.x >> 5;
    const int r0 = (blockIdx.x & 31) * 32;
    const int t  = threadIdx.x;

    const __half2* src = g_os2 + (size_t)b * (NV / 2) * NR + r0;
#pragma unroll
    for (int i = 0; i < 4; i++) {
        int idx = t + 512 * i;             // 0..2047 -> 128 vp x 16 rlp
        int vp = idx >> 4, rlp = idx & 15;
        uint2 q = *(const uint2*)(src + (size_t)vp * NR + 2 * rlp);
        __half2 h0 = u2h(q.x);             // (vA, vB) @ r
        __half2 h1 = u2h(q.y);             // (vA, vB) @ r+1
        tile[2 * vp][rlp]     = make_float2(__low2float(h0),  __low2float(h1));
        tile[2 * vp + 1][rlp] = make_float2(__high2float(h0), __high2float(h1));
    }
    __syncthreads();

    const int rlp = t & 15;
    const int v0  = (t >> 4) * 8;          // 32 segments of 8 v's

    float2 b21 = make_float2(0.f, 0.f), b5 = make_float2(0.f, 0.f);
#pragma unroll
    for (int d = -10; d <= 10; d++) {
        float2 x = tile[(v0 + d) & (NV - 1)][rlp];
        b21.x += x.x; b21.y += x.y;
        if (d >= -2 && d <= 2) { b5.x += x.x; b5.y += x.y; }
    }

    float* dst = out + (size_t)b * NV * NR + r0 + 2 * rlp;
#pragma unroll
    for (int vi = 0; vi < 8; vi++) {
        const int v = v0 + vi;
        float2 o = make_float2(b21.x - b5.x, b21.y - b5.y);
        *(float2*)(dst + (size_t)v * NR) = o;
        float2 p21 = tile[(v + 11) & (NV - 1)][rlp];
        float2 m21 = tile[(v - 10) & (NV - 1)][rlp];
        float2 p5  = tile[(v + 3)  & (NV - 1)][rlp];
        float2 m5  = tile[(v - 2)  & (NV - 1)][rlp];
        b21.x += p21.x - m21.x; b21.y += p21.y - m21.y;
        b5.x  += p5.x  - m5.x;  b5.y  += p5.y  - m5.y;
    }
}

// ---------------- host: replicate the reference's alpha solve ----------------

static double cfar_log_factorial(double n) {
    n += 1.0;
    if (n < 9.0) {
        double f = 1.0;
        int m = (int)(n + 0.5);
        for (int i = 2; i <= m; i++) f *= (double)i;
        return log(f);
    }
    return 0.5 * (log(2.0 * 3.14159265358979323846) - log(n))
         + n * (log(n + 1.0 / (12.0 * n - 1.0 / (10.0 * n))) - 1.0);
}

static double cfar_fun(int k, int n, double t, double pfa) {
    double s = 0.0;
    for (int j = n; j > n - k; j--) s += log((double)j + t);
    return cfar_log_factorial((double)n) - cfar_log_factorial((double)(n - k)) - s - log(pfa);
}

extern "C" void kernel_launch(void* const* d_in, const int* in_sizes, int n_in,
                              void* d_out, int out_size) {
    (void)in_sizes; (void)n_in; (void)out_size;
    const float* data = (const float*)d_in[0];
    float* out = (float*)d_out;

    double lo = 1.0, hi = 1.0e6;
    for (int it = 0; it < 200; it++) {
        double mid = 0.5 * (lo + hi);
        if (cfar_fun(24, 32, mid, 1.0e-5) > 0.0) lo = mid; else hi = mid;
    }
    float alpha_eff = (float)(sqrt(0.5 * (lo + hi)) / 16.0);   // alpha/16, CA divisor folded

    const int OS_SMEM = 4160 + 2 * 33792;   // 71744 B
    cudaFuncSetAttribute(os5_kernel, cudaFuncAttributeMaxDynamicSharedMemorySize, OS_SMEM);

    os5_kernel<<<NB * NV / 2, 512, OS_SMEM>>>(data, alpha_eff);
    ca3_kernel<<<NB * 32, 512>>>(out);
}

// round 8
// speedup vs baseline: 1.1660x; 1.0013x over previous
#include <cuda_runtime.h>
#include <cuda_fp16.h>
#include <math.h>

#define NB 16
#define NV 256
#define NR 1024
#define RMASK 1023

#define CSL 546    // L-table position stride (545 used)
#define CSM 538    // M-table position stride (538 used)

// OS-CFAR intermediate: half2 packs two adjacent v-rows; values pre-scaled by alpha/16. 8.4 MB.
__device__ __half2 g_os2[(NB * NV / 2) * NR];

#define CAS2(a, b) do { __half2 _hi = __hmax2(a, b); __half2 _lo = __hmin2(a, b); (a) = _hi; (b) = _lo; } while (0)

__device__ __forceinline__ __half2 u2h(unsigned u) { return *(__half2*)&u; }
__device__ __forceinline__ unsigned h2u(__half2 h) { return *(unsigned*)&h; }

// Batcher odd-even mergesort, 8 elems, descending (19 comparators).
__device__ __forceinline__ void sort8h(__half2* x) {
    CAS2(x[0], x[1]); CAS2(x[2], x[3]); CAS2(x[0], x[2]); CAS2(x[1], x[3]); CAS2(x[1], x[2]);
    CAS2(x[4], x[5]); CAS2(x[6], x[7]); CAS2(x[4], x[6]); CAS2(x[5], x[7]); CAS2(x[5], x[6]);
    CAS2(x[0], x[4]); CAS2(x[2], x[6]); CAS2(x[2], x[4]);
    CAS2(x[1], x[5]); CAS2(x[3], x[7]); CAS2(x[3], x[5]);
    CAS2(x[1], x[2]); CAS2(x[3], x[4]); CAS2(x[5], x[6]);
}

// M = sorted-desc top-8 of (sorted a) U (sorted b): half-cleaner + bitonic sort-8.
__device__ __forceinline__ void merge_top8(const __half2* a, const __half2* b, __half2* m) {
    m[0] = __hmax2(a[0], b[7]); m[1] = __hmax2(a[1], b[6]);
    m[2] = __hmax2(a[2], b[5]); m[3] = __hmax2(a[3], b[4]);
    m[4] = __hmax2(a[4], b[3]); m[5] = __hmax2(a[5], b[2]);
    m[6] = __hmax2(a[6], b[1]); m[7] = __hmax2(a[7], b[0]);
    CAS2(m[0], m[4]); CAS2(m[1], m[5]); CAS2(m[2], m[6]); CAS2(m[3], m[7]);
    CAS2(m[0], m[2]); CAS2(m[1], m[3]); CAS2(m[4], m[6]); CAS2(m[5], m[7]);
    CAS2(m[0], m[1]); CAS2(m[2], m[3]); CAS2(m[4], m[5]); CAS2(m[6], m[7]);
}

// 8th largest of union of two sorted-desc-8 lists = min_i max(A[i], B[7-i]).
__device__ __forceinline__ __half2 kth8(const __half2* a, const __half2* b) {
    __half2 m0 = __hmin2(__hmax2(a[0], b[7]), __hmax2(a[1], b[6]));
    __half2 m1 = __hmin2(__hmax2(a[2], b[5]), __hmax2(a[3], b[4]));
    __half2 m2 = __hmin2(__hmax2(a[4], b[3]), __hmax2(a[5], b[2]));
    __half2 m3 = __hmin2(__hmax2(a[6], b[1]), __hmax2(a[7], b[0]));
    return __hmin2(__hmin2(m0, m1), __hmin2(m2, m3));
}

// OS kernel v6: split-r. Block = (v-pair, r-half of 512 outputs); 256 threads; ~37KB smem
// -> 5 blocks/SM resident, cheap 256-thread barriers.
// Local coord q: position p = r0 - 20 + q. Tables packed as os5:
//   T[(c2*CS + q)*2 + j] holds list(q)[2c2+j]; uint4 at even q = {list(q), list(q+1)} x 2 cols.
// Thread t: primary L/M at q = 2t, 2t+1; outputs r = r0+2t, r0+2t+1.
// Halo: t<17 build extra L at q=512+2t; t<13 extra M at q=512+2t; t<26 extra row loads.
__global__ void __launch_bounds__(256, 5) os6_kernel(const float* __restrict__ data, float ae) {
    __shared__ __half2 row2[564];
    __shared__ __half2 Lt[4 * CSL * 2];
    __shared__ __half2 Mt[4 * CSM * 2];

    const int t  = threadIdx.x;
    const int vp = blockIdx.x >> 1;
    const int r0 = (blockIdx.x & 1) << 9;

    const float2* srcA = (const float2*)(data + (size_t)(2 * vp) * NR);
    const float2* srcB = (const float2*)(data + (size_t)(2 * vp + 1) * NR);

    {   // rows q2 = 2t (+ halo): row2[q2] = half2(rowA, rowB) at r = r0-20+q2, scaled.
        int r = (r0 - 20 + 2 * t) & RMASK;
        float2 fa = srcA[r >> 1], fb = srcB[r >> 1];
        row2[2 * t]     = __floats2half2_rn(fa.x * ae, fb.x * ae);
        row2[2 * t + 1] = __floats2half2_rn(fa.y * ae, fb.y * ae);
        if (t < 26) {
            int r2 = (r0 + 492 + 2 * t) & RMASK;
            float2 ga = srcA[r2 >> 1], gb = srcB[r2 >> 1];
            row2[512 + 2 * t]     = __floats2half2_rn(ga.x * ae, gb.x * ae);
            row2[512 + 2 * t + 1] = __floats2half2_rn(ga.y * ae, gb.y * ae);
        }
    }
    __syncthreads();

    // Phase A: L(2t), L(2t+1) in registers; publish packed. Halo L for t<17.
    __half2 La[8], Lb[8];
    {
        __half2 r[10];
        const uint2* rp = (const uint2*)(row2 + 2 * t);
#pragma unroll
        for (int k = 0; k < 5; k++) {
            uint2 q = rp[k];
            r[2 * k] = u2h(q.x); r[2 * k + 1] = u2h(q.y);
        }
#pragma unroll
        for (int i = 0; i < 8; i++) { La[i] = r[i]; Lb[i] = r[i + 1]; }
    }
    sort8h(La);
    sort8h(Lb);
#pragma unroll
    for (int c2 = 0; c2 < 4; c2++) {
        uint4 w;
        w.x = h2u(La[2 * c2]); w.y = h2u(La[2 * c2 + 1]);
        w.z = h2u(Lb[2 * c2]); w.w = h2u(Lb[2 * c2 + 1]);
        *(uint4*)(Lt + (c2 * CSL + 2 * t) * 2) = w;
    }
    if (t < 17) {   // halo L at q = 512+2t, 513+2t
        __half2 r[10], Ha[8], Hb[8];
        const uint2* rp = (const uint2*)(row2 + 512 + 2 * t);
#pragma unroll
        for (int k = 0; k < 5; k++) {
            uint2 q = rp[k];
            r[2 * k] = u2h(q.x); r[2 * k + 1] = u2h(q.y);
        }
#pragma unroll
        for (int i = 0; i < 8; i++) { Ha[i] = r[i]; Hb[i] = r[i + 1]; }
        sort8h(Ha);
        sort8h(Hb);
#pragma unroll
        for (int c2 = 0; c2 < 4; c2++) {
            uint4 w;
            w.x = h2u(Ha[2 * c2]); w.y = h2u(Ha[2 * c2 + 1]);
            w.z = h2u(Hb[2 * c2]); w.w = h2u(Hb[2 * c2 + 1]);
            *(uint4*)(Lt + (c2 * CSL + 512 + 2 * t) * 2) = w;
        }
    }
    __syncthreads();

    // Phase B: M(q) = merge(L(q), L(q+8)). Primary in regs; halo M for t<13 (both from table).
    __half2 M0[8], M1[8];
    {
        __half2 xb[8], yb[8];
#pragma unroll
        for (int c2 = 0; c2 < 4; c2++) {
            uint4 q = *(const uint4*)(Lt + (c2 * CSL + 2 * t + 8) * 2);
            xb[2 * c2] = u2h(q.x); xb[2 * c2 + 1] = u2h(q.y);
            yb[2 * c2] = u2h(q.z); yb[2 * c2 + 1] = u2h(q.w);
        }
        merge_top8(La, xb, M0);
        merge_top8(Lb, yb, M1);
    }
#pragma unroll
    for (int c2 = 0; c2 < 4; c2++) {
        uint4 w;
        w.x = h2u(M0[2 * c2]); w.y = h2u(M0[2 * c2 + 1]);
        w.z = h2u(M1[2 * c2]); w.w = h2u(M1[2 * c2 + 1]);
        *(uint4*)(Mt + (c2 * CSM + 2 * t) * 2) = w;
    }
    if (t < 13) {   // halo M at q = 512+2t, 513+2t
        __half2 pa[8], pb[8], qa[8], qb[8], H0[8], H1[8];
#pragma unroll
        for (int c2 = 0; c2 < 4; c2++) {
            uint4 u = *(const uint4*)(Lt + (c2 * CSL + 512 + 2 * t) * 2);
            pa[2 * c2] = u2h(u.x); pa[2 * c2 + 1] = u2h(u.y);
            pb[2 * c2] = u2h(u.z); pb[2 * c2 + 1] = u2h(u.w);
            uint4 v = *(const uint4*)(Lt + (c2 * CSL + 520 + 2 * t) * 2);
            qa[2 * c2] = u2h(v.x); qa[2 * c2 + 1] = u2h(v.y);
            qb[2 * c2] = u2h(v.z); qb[2 * c2 + 1] = u2h(v.w);
        }
        merge_top8(pa, qa, H0);
        merge_top8(pb, qb, H1);
#pragma unroll
        for (int c2 = 0; c2 < 4; c2++) {
            uint4 w;
            w.x = h2u(H0[2 * c2]); w.y = h2u(H0[2 * c2 + 1]);
            w.z = h2u(H1[2 * c2]); w.w = h2u(H1[2 * c2 + 1]);
            *(uint4*)(Mt + (c2 * CSM + 512 + 2 * t) * 2) = w;
        }
    }
    __syncthreads();

    // Phase C: outputs r = r0+2t, r0+2t+1 use M(q=2t) [regs] and M(q=2t+25), M(q=2t+26).
    __half2 n0[8], n1[8];
#pragma unroll
    for (int c2 = 0; c2 < 4; c2++) {
        uint2 qa = *(const uint2*)(Mt + (c2 * CSM + 2 * t + 25) * 2);
        n0[2 * c2] = u2h(qa.x); n0[2 * c2 + 1] = u2h(qa.y);
        uint2 qb = *(const uint2*)(Mt + (c2 * CSM + 2 * t + 26) * 2);
        n1[2 * c2] = u2h(qb.x); n1[2 * c2 + 1] = u2h(qb.y);
    }
    __half2 os0 = kth8(M0, n0);
    __half2 os1 = kth8(M1, n1);

    __half2* g2 = g_os2 + (size_t)vp * NR + r0;
    uint2 o; o.x = h2u(os0); o.y = h2u(os1);
    *(uint2*)&g2[2 * t] = o;
}

// CA kernel (best-measured form): out(v) = box21(v) - box5(v); alpha/16 pre-folded.
// Block = (batch, 32-wide r chunk); tile unpacked fp32 in smem.
__global__ void __launch_bounds__(512) ca_kernel(float* __restrict__ out) {
    __shared__ float tile[NV][32];
    const int b  = blockIdx.x >> 5;
    const int r0 = (blockIdx.x & 31) * 32;
    const int t  = threadIdx.x;

    const __half2* src = g_os2 + (size_t)b * (NV / 2) * NR + r0;
#pragma unroll
    for (int i = 0; i < 8; i++) {
        int idx = t + 512 * i;             // 0..4095 -> 128 vp x 32 rl
        int vp = idx >> 5, rl = idx & 31;
        __half2 v2 = src[(size_t)vp * NR + rl];
        tile[2 * vp][rl]     = __low2float(v2);
        tile[2 * vp + 1][rl] = __high2float(v2);
    }
    __syncthreads();

    const int rl = t & 31;
    const int v0 = (t >> 5) * 16;

    float box21 = 0.0f, box5 = 0.0f;
#pragma unroll
    for (int d = -10; d <= 10; d++) {
        float x = tile[(v0 + d) & (NV - 1)][rl];
        box21 += x;
        if (d >= -2 && d <= 2) box5 += x;
    }

    float* dst = out + (size_t)b * NV * NR + r0 + rl;
#pragma unroll
    for (int vi = 0; vi < 16; vi++) {
        const int v = v0 + vi;
        dst[(size_t)v * NR] = box21 - box5;
        box21 += tile[(v + 11) & (NV - 1)][rl] - tile[(v - 10) & (NV - 1)][rl];
        box5  += tile[(v + 3)  & (NV - 1)][rl] - tile[(v - 2)  & (NV - 1)][rl];
    }
}

// ---------------- host: replicate the reference's alpha solve ----------------

static double cfar_log_factorial(double n) {
    n += 1.0;
    if (n < 9.0) {
        double f = 1.0;
        int m = (int)(n + 0.5);
        for (int i = 2; i <= m; i++) f *= (double)i;
        return log(f);
    }
    return 0.5 * (log(2.0 * 3.14159265358979323846) - log(n))
         + n * (log(n + 1.0 / (12.0 * n - 1.0 / (10.0 * n))) - 1.0);
}

static double cfar_fun(int k, int n, double t, double pfa) {
    double s = 0.0;
    for (int j = n; j > n - k; j--) s += log((double)j + t);
    return cfar_log_factorial((double)n) - cfar_log_factorial((double)(n - k)) - s - log(pfa);
}

extern "C" void kernel_launch(void* const* d_in, const int* in_sizes, int n_in,
                              void* d_out, int out_size) {
    (void)in_sizes; (void)n_in; (void)out_size;
    const float* data = (const float*)d_in[0];
    float* out = (float*)d_out;

    double lo = 1.0, hi = 1.0e6;
    for (int it = 0; it < 200; it++) {
        double mid = 0.5 * (lo + hi);
        if (cfar_fun(24, 32, mid, 1.0e-5) > 0.0) lo = mid; else hi = mid;
    }
    float alpha_eff = (float)(sqrt(0.5 * (lo + hi)) / 16.0);   // alpha/16, CA divisor folded

    os6_kernel<<<NB * NV, 256>>>(data, alpha_eff);   // 4096 blocks: (v-pair, r-half)
    ca_kernel<<<NB * 32, 512>>>(out);
}